// round 14
// baseline (speedup 1.0000x reference)
#include <cuda_runtime.h>
#include <cuda_bf16.h>
#include <cstdint>

#define S_LEN 2048
#define BATCH 64
#define IDIM  256
#define HDIM  512
#define GATE3 1536

#define NGROUPS 8
#define GCTAS   16
#define NB      8
#define CCOLS   32

// -------------------- device scratch (no cudaMalloc allowed) ---------------
__device__ float g_Xp[(size_t)S_LEN * BATCH * GATE3];   // [s][b][1536], bias folded
__device__ float g_hG [NGROUPS * HDIM * NB];            // [g][k][8] group-local
__device__ float g_rhG[NGROUPS * HDIM * NB];            // [g][k][8]
// monotonic crossing counters, 1KB stride per group (distinct L2 lines)
__device__ __align__(128) unsigned g_c1[NGROUPS * 256];
__device__ __align__(128) unsigned g_c2[NGROUPS * 256];

// -------------------- packed fp32x2 helpers --------------------------------
#define FMA2(d, a, b) \
    asm("fma.rn.f32x2 %0, %1, %2, %0;" : "+l"(d) : "l"(a), "l"(b))

__device__ __forceinline__ unsigned long long splat2(float u) {
    unsigned long long uu;
    asm("mov.b64 %0, {%1, %1};" : "=l"(uu) : "f"(u));
    return uu;
}
__device__ __forceinline__ unsigned long long pack2(float lo, float hi) {
    unsigned long long r;
    asm("mov.b64 %0, {%1, %2};" : "=l"(r) : "f"(lo), "f"(hi));
    return r;
}
__device__ __forceinline__ float2 unpack2(unsigned long long v) {
    float2 r;
    asm("mov.b64 {%0, %1}, %2;" : "=f"(r.x), "=f"(r.y) : "l"(v));
    return r;
}

__device__ __forceinline__ float sigm(float x) { return 1.f / (1.f + __expf(-x)); }

// -------------------- scoped atomics / loads --------------------------------
__device__ __forceinline__ unsigned atom_add_acqrel(unsigned* p, unsigned v) {
    unsigned old;
    asm volatile("atom.add.acq_rel.gpu.global.u32 %0, [%1], %2;"
                 : "=r"(old) : "l"(p), "r"(v) : "memory");
    return old;
}
__device__ __forceinline__ unsigned ld_relaxed_g(const unsigned* p) {
    unsigned v;
    asm volatile("ld.relaxed.gpu.global.u32 %0, [%1];" : "=r"(v) : "l"(p) : "memory");
    return v;
}
__device__ __forceinline__ unsigned ld_acquire_g(const unsigned* p) {
    unsigned v;
    asm volatile("ld.acquire.gpu.global.u32 %0, [%1];" : "=r"(v) : "l"(p) : "memory");
    return v;
}

// Split barrier on monotonic counters (16 arrivals per crossing, no reset).
__device__ __forceinline__ void g_arrive(unsigned* c) {
    __syncthreads();                       // all CTA stores precede the release-add
    if (threadIdx.x == 0) atom_add_acqrel(c, 1u);
}
__device__ __forceinline__ void g_wait(const unsigned* c, unsigned target) {
    if (threadIdx.x == 0) {
        if (ld_relaxed_g(c) < target) {
            do { __nanosleep(40); } while (ld_relaxed_g(c) < target);
        }
        (void)ld_acquire_g(c);
    }
    __syncthreads();
}

// ===========================================================================
// Kernel 1: Xp[s][b][c] = x[b][s][:] . W_g[c] + bias_g[c]   (unchanged, R8)
// ===========================================================================
__global__ __launch_bounds__(256) void pregemm_kernel(
    const float* __restrict__ x,
    const float* __restrict__ Wz, const float* __restrict__ Wr, const float* __restrict__ Wh,
    const float* __restrict__ bz, const float* __restrict__ br, const float* __restrict__ bh)
{
    __shared__ float As[16][132];
    __shared__ float Bs[16][68];

    const int tid = threadIdx.x;
    const int m0  = blockIdx.x * 128;
    const int c0g = blockIdx.y * 64;

    const float* W; const float* bias; int cr;
    if (c0g < 512)       { W = Wz; bias = bz; cr = c0g; }
    else if (c0g < 1024) { W = Wr; bias = br; cr = c0g - 512; }
    else                 { W = Wh; bias = bh; cr = c0g - 1024; }

    const int arow = tid >> 2;
    const int ak   = (tid & 3) << 2;
    const int bcol = tid >> 2;
    const int bk   = (tid & 3) << 2;
    const int ty   = tid >> 4;
    const int tx   = tid & 15;

    const float* xA0 = x + (size_t)(m0 + arow)      * IDIM + ak;
    const float* xA1 = x + (size_t)(m0 + arow + 64) * IDIM + ak;
    const float* wB  = W + (size_t)(cr + bcol)      * IDIM + bk;

    float4 a0 = *(const float4*)(xA0);
    float4 a1 = *(const float4*)(xA1);
    float4 b0 = *(const float4*)(wB);

    unsigned long long acc2[8][2];
#pragma unroll
    for (int i = 0; i < 8; i++) { acc2[i][0] = 0ull; acc2[i][1] = 0ull; }

    for (int kt = 0; kt < IDIM; kt += 16) {
        As[ak+0][arow]    = a0.x; As[ak+1][arow]    = a0.y;
        As[ak+2][arow]    = a0.z; As[ak+3][arow]    = a0.w;
        As[ak+0][arow+64] = a1.x; As[ak+1][arow+64] = a1.y;
        As[ak+2][arow+64] = a1.z; As[ak+3][arow+64] = a1.w;
        Bs[bk+0][bcol] = b0.x; Bs[bk+1][bcol] = b0.y;
        Bs[bk+2][bcol] = b0.z; Bs[bk+3][bcol] = b0.w;
        __syncthreads();

        if (kt < IDIM - 16) {
            a0 = *(const float4*)(xA0 + kt + 16);
            a1 = *(const float4*)(xA1 + kt + 16);
            b0 = *(const float4*)(wB  + kt + 16);
        }

#pragma unroll
        for (int kk = 0; kk < 16; kk++) {
            float4 rA0 = *(const float4*)&As[kk][ty * 8];
            float4 rA1 = *(const float4*)&As[kk][ty * 8 + 4];
            float4 rBf = *(const float4*)&Bs[kk][tx * 4];
            unsigned long long b01 = pack2(rBf.x, rBf.y);
            unsigned long long b23 = pack2(rBf.z, rBf.w);
            unsigned long long s;
            s = splat2(rA0.x); FMA2(acc2[0][0], s, b01); FMA2(acc2[0][1], s, b23);
            s = splat2(rA0.y); FMA2(acc2[1][0], s, b01); FMA2(acc2[1][1], s, b23);
            s = splat2(rA0.z); FMA2(acc2[2][0], s, b01); FMA2(acc2[2][1], s, b23);
            s = splat2(rA0.w); FMA2(acc2[3][0], s, b01); FMA2(acc2[3][1], s, b23);
            s = splat2(rA1.x); FMA2(acc2[4][0], s, b01); FMA2(acc2[4][1], s, b23);
            s = splat2(rA1.y); FMA2(acc2[5][0], s, b01); FMA2(acc2[5][1], s, b23);
            s = splat2(rA1.z); FMA2(acc2[6][0], s, b01); FMA2(acc2[6][1], s, b23);
            s = splat2(rA1.w); FMA2(acc2[7][0], s, b01); FMA2(acc2[7][1], s, b23);
        }
        __syncthreads();
    }

    float4 bv = *(const float4*)(bias + cr + (tx << 2));
#pragma unroll
    for (int i = 0; i < 8; i++) {
        int mm   = m0 + ty * 8 + i;
        int srow = mm & (S_LEN - 1);
        int bb   = mm >> 11;
        size_t off = ((size_t)(srow * BATCH + bb)) * GATE3 + c0g + (tx << 2);
        float2 p01 = unpack2(acc2[i][0]);
        float2 p23 = unpack2(acc2[i][1]);
        float4 v;
        v.x = p01.x + bv.x; v.y = p01.y + bv.y;
        v.z = p23.x + bv.z; v.w = p23.y + bv.w;
        *(float4*)(g_Xp + off) = v;
    }
}

// ===========================================================================
// Kernel 2: persistent GRU scan, 2-way group-multiplexed.
// Grid = 64 CTAs (4 sets x 16); CTA serves groups 2*set and 2*set+1.
// SMEM (floats): Uz[512][33] | Ur[512][33] | Uh[512][33] | hs[512][8] |
//                red[256][8] | zsA[256] | zsB[256]
// ===========================================================================
#define UZ_OFF  0
#define UR_OFF  16896
#define UH_OFF  33792
#define HS_OFF  50688
#define RED_OFF 54784
#define ZSA_OFF 56832
#define ZSB_OFF 57088
#define SMEM_FLOATS 57344      // 229376 bytes

__device__ __forceinline__ void stage_hs(float* sm, const float* src, int tid) {
#pragma unroll
    for (int i = 0; i < 4; i++)
        *(float4*)(sm + HS_OFF + (tid + i * 256) * 4) =
            *(const float4*)(src + (tid + i * 256) * 4);
}

__device__ __forceinline__ void p1_matvec(float* sm, int warp, int lane) {
    const int gate = warp >> 2;           // 0=z, 1=r
    const int ks   = warp & 3;            // k-split of 128
    const float* Ub = sm + (gate ? UR_OFF : UZ_OFF);
    unsigned long long a0 = 0, a1 = 0, a2 = 0, a3 = 0;
    const int k0 = ks * 128;
#pragma unroll 4
    for (int k = k0; k < k0 + 128; k++) {
        unsigned long long uu = splat2(Ub[k * 33 + lane]);
        const ulonglong2* hp = (const ulonglong2*)(sm + HS_OFF + k * 8);
        ulonglong2 hA = hp[0], hB = hp[1];
        FMA2(a0, uu, hA.x);
        FMA2(a1, uu, hA.y);
        FMA2(a2, uu, hB.x);
        FMA2(a3, uu, hB.y);
    }
    float* rp = sm + RED_OFF + (ks * 64 + gate * 32 + lane) * 8;
    ulonglong2 s0; s0.x = a0; s0.y = a1;
    ulonglong2 s1; s1.x = a2; s1.y = a3;
    *(ulonglong2*)(rp)     = s0;
    *(ulonglong2*)(rp + 4) = s1;
}

__device__ __forceinline__ void p2_matvec(float* sm, int warp, int lane) {
    const int ks = warp;                  // k-split of 64
    const float* Ub = sm + UH_OFF;
    unsigned long long a0 = 0, a1 = 0, a2 = 0, a3 = 0;
    const int k0 = ks * 64;
#pragma unroll 4
    for (int k = k0; k < k0 + 64; k++) {
        unsigned long long uu = splat2(Ub[k * 33 + lane]);
        const ulonglong2* hp = (const ulonglong2*)(sm + HS_OFF + k * 8);
        ulonglong2 hA = hp[0], hB = hp[1];
        FMA2(a0, uu, hA.x);
        FMA2(a1, uu, hA.y);
        FMA2(a2, uu, hB.x);
        FMA2(a3, uu, hB.y);
    }
    float* rp = sm + RED_OFF + (ks * 32 + lane) * 8;
    ulonglong2 s0; s0.x = a0; s0.y = a1;
    ulonglong2 s1; s1.x = a2; s1.y = a3;
    *(ulonglong2*)(rp)     = s0;
    *(ulonglong2*)(rp + 4) = s1;
}

__global__ __launch_bounds__(256, 1) void scan_kernel(
    const float* __restrict__ Uz, const float* __restrict__ Ur, const float* __restrict__ Uh,
    const float* __restrict__ cz, const float* __restrict__ cr, const float* __restrict__ ch)
{
    extern __shared__ float sm[];
    const int tid  = threadIdx.x;
    const int set  = blockIdx.x >> 4;     // 0..3
    const int ctg  = blockIdx.x & 15;     // cta within set
    const int cbase = ctg * CCOLS;
    const int gA = set * 2;
    const int gB = set * 2 + 1;

    // ---- load U tiles transposed (shared by both groups — same columns)
    {
        const float* Us_src[3] = { Uz, Ur, Uh };
        float* Us_dst[3] = { sm + UZ_OFF, sm + UR_OFF, sm + UH_OFF };
#pragma unroll
        for (int gate = 0; gate < 3; gate++) {
            const float* U = Us_src[gate];
            float* D = Us_dst[gate];
            for (int i = tid; i < CCOLS * 128; i += 256) {
                int c  = i >> 7;
                int k4 = (i & 127) << 2;
                float4 v = *(const float4*)(U + (size_t)(cbase + c) * HDIM + k4);
                D[(k4+0)*33 + c] = v.x;
                D[(k4+1)*33 + c] = v.y;
                D[(k4+2)*33 + c] = v.z;
                D[(k4+3)*33 + c] = v.w;
            }
        }
    }

    const int warp = tid >> 5;
    const int lane = tid & 31;
    const int rc = tid >> 3;        // reduction col 0..31
    const int rb = tid & 7;         // reduction batch 0..7
    const int gcol = cbase + rc;
    const int gbA = gA * NB + rb;
    const int gbB = gB * NB + rb;

    const float czv = cz[gcol];
    const float crv = cr[gcol];
    const float chv = ch[gcol];

    float* hA_g  = g_hG  + gA * (HDIM * NB);
    float* hB_g  = g_hG  + gB * (HDIM * NB);
    float* rhA_g = g_rhG + gA * (HDIM * NB);
    float* rhB_g = g_rhG + gB * (HDIM * NB);
    unsigned* c1A = &g_c1[gA * 256];
    unsigned* c1B = &g_c1[gB * 256];
    unsigned* c2A = &g_c2[gA * 256];
    unsigned* c2B = &g_c2[gB * 256];

    const float* rd = sm + RED_OFF;

    __syncthreads();

    for (int s = 0; s < S_LEN; s++) {
        const unsigned tprev = 16u * (unsigned)s;
        const unsigned tcur  = tprev + 16u;

        // prefetch x-projections for both groups (consumed much later)
        const float* xpA = g_Xp + ((size_t)s * BATCH + gbA) * GATE3 + gcol;
        float xzA = xpA[0], xrA = xpA[512], xhA = xpA[1024];
        const float* xpB = g_Xp + ((size_t)s * BATCH + gbB) * GATE3 + gcol;
        float xzB = xpB[0], xrB = xpB[512], xhB = xpB[1024];

        // ================= P1 for group A =================
        g_wait(c2A, tprev);
        stage_hs(sm, hA_g, tid);
        __syncthreads();
        p1_matvec(sm, warp, lane);
        __syncthreads();
        float zsumA = rd[(rc)*8+rb] + rd[(64+rc)*8+rb] + rd[(128+rc)*8+rb] + rd[(192+rc)*8+rb];
        float rsumA = rd[(32+rc)*8+rb] + rd[(96+rc)*8+rb] + rd[(160+rc)*8+rb] + rd[(224+rc)*8+rb];
        float zA = sigm(zsumA + xzA + czv);
        float rA = sigm(rsumA + xrA + crv);
        float holdA = sm[HS_OFF + gcol * 8 + rb];
        sm[ZSA_OFF + rc * 8 + rb] = zA;
        rhA_g[gcol * NB + rb] = rA * holdA;
        g_arrive(c1A);

        // ================= P1 for group B =================
        g_wait(c2B, tprev);
        stage_hs(sm, hB_g, tid);
        __syncthreads();
        p1_matvec(sm, warp, lane);
        __syncthreads();
        float zsumB = rd[(rc)*8+rb] + rd[(64+rc)*8+rb] + rd[(128+rc)*8+rb] + rd[(192+rc)*8+rb];
        float rsumB = rd[(32+rc)*8+rb] + rd[(96+rc)*8+rb] + rd[(160+rc)*8+rb] + rd[(224+rc)*8+rb];
        float zB = sigm(zsumB + xzB + czv);
        float rB = sigm(rsumB + xrB + crv);
        float holdB = sm[HS_OFF + gcol * 8 + rb];
        sm[ZSB_OFF + rc * 8 + rb] = zB;
        rhB_g[gcol * NB + rb] = rB * holdB;
        g_arrive(c1B);

        // ================= P2 for group A =================
        g_wait(c1A, tcur);
        stage_hs(sm, rhA_g, tid);
        __syncthreads();
        p2_matvec(sm, warp, lane);
        __syncthreads();
        {
            float hsum = 0.f;
#pragma unroll
            for (int ks = 0; ks < 8; ks++)
                hsum += rd[(ks * 32 + rc) * 8 + rb];
            float htil = tanhf(hsum + xhA + chv);
            float z2 = sm[ZSA_OFF + rc * 8 + rb];
            hA_g[gcol * NB + rb] = holdA + z2 * (htil - holdA);
        }
        g_arrive(c2A);

        // ================= P2 for group B =================
        g_wait(c1B, tcur);
        stage_hs(sm, rhB_g, tid);
        __syncthreads();
        p2_matvec(sm, warp, lane);
        __syncthreads();
        {
            float hsum = 0.f;
#pragma unroll
            for (int ks = 0; ks < 8; ks++)
                hsum += rd[(ks * 32 + rc) * 8 + rb];
            float htil = tanhf(hsum + xhB + chv);
            float z2 = sm[ZSB_OFF + rc * 8 + rb];
            hB_g[gcol * NB + rb] = holdB + z2 * (htil - holdB);
        }
        g_arrive(c2B);
    }
}

// ===========================================================================
// Kernel 3: out[b][o] = sum_j h[g(b)][j][b&7] * Wf[o][j] + bf[o]
// ===========================================================================
__global__ __launch_bounds__(640) void outgemm_kernel(
    const float* __restrict__ Wf, const float* __restrict__ bf, float* __restrict__ out)
{
    int t = threadIdx.x;
    if (t >= 640) return;
    int b = t / 10, o = t % 10;
    const float* hb = g_hG + (b >> 3) * (HDIM * NB) + (b & 7);
    float acc = 0.f;
#pragma unroll 8
    for (int j = 0; j < HDIM; j++)
        acc += hb[j * NB] * Wf[o * HDIM + j];
    out[b * 10 + o] = acc + bf[o];
}

// ===========================================================================
extern "C" void kernel_launch(void* const* d_in, const int* in_sizes, int n_in,
                              void* d_out, int out_size)
{
    const float* x  = (const float*)d_in[0];
    const float* Wz = (const float*)d_in[1];
    const float* bz = (const float*)d_in[2];
    const float* Uz = (const float*)d_in[3];
    const float* cz = (const float*)d_in[4];
    const float* Wr = (const float*)d_in[5];
    const float* br = (const float*)d_in[6];
    const float* Ur = (const float*)d_in[7];
    const float* cr = (const float*)d_in[8];
    const float* Wh = (const float*)d_in[9];
    const float* bh = (const float*)d_in[10];
    const float* Uh = (const float*)d_in[11];
    const float* ch = (const float*)d_in[12];
    const float* Wf = (const float*)d_in[13];
    const float* bf = (const float*)d_in[14];
    float* out = (float*)d_out;

    void *p_h, *p_c1, *p_c2;
    cudaGetSymbolAddress(&p_h,  g_hG);
    cudaGetSymbolAddress(&p_c1, g_c1);
    cudaGetSymbolAddress(&p_c2, g_c2);

    cudaMemsetAsync(p_h,  0, NGROUPS * HDIM * NB * sizeof(float));
    cudaMemsetAsync(p_c1, 0, NGROUPS * 256 * sizeof(unsigned int));
    cudaMemsetAsync(p_c2, 0, NGROUPS * 256 * sizeof(unsigned int));

    pregemm_kernel<<<dim3(1024, 24), 256>>>(x, Wz, Wr, Wh, bz, br, bh);

    cudaFuncSetAttribute(scan_kernel, cudaFuncAttributeMaxDynamicSharedMemorySize,
                         SMEM_FLOATS * sizeof(float));
    scan_kernel<<<64, 256, SMEM_FLOATS * sizeof(float)>>>(Uz, Ur, Uh, cz, cr, ch);

    outgemm_kernel<<<1, 640>>>(Wf, bf, out);
}

// round 16
// speedup vs baseline: 1.6332x; 1.6332x over previous
#include <cuda_runtime.h>
#include <cuda_bf16.h>
#include <cstdint>

#define S_LEN 2048
#define BATCH 64
#define IDIM  256
#define HDIM  512
#define GATE3 1536

#define NGROUPS 8
#define GCTAS   16
#define NB      8
#define CCOLS   32

// -------------------- device scratch (no cudaMalloc allowed) ---------------
__device__ float g_Xp[(size_t)S_LEN * BATCH * GATE3];   // [s][b][1536], bias folded
__device__ float g_hG [NGROUPS * HDIM * NB];            // [g][k][8] group-local
__device__ float g_rhG[NGROUPS * HDIM * NB];            // [g][k][8]
// barrier counters: 1KB stride -> distinct L2 lines/slices
__device__ __align__(128) unsigned g_cnt[NGROUPS * 256];
__device__ __align__(128) unsigned g_gen[NGROUPS * 256];

// -------------------- packed fp32x2 helpers --------------------------------
#define FMA2(d, a, b) \
    asm("fma.rn.f32x2 %0, %1, %2, %0;" : "+l"(d) : "l"(a), "l"(b))

__device__ __forceinline__ unsigned long long splat2(float u) {
    unsigned long long uu;
    asm("mov.b64 %0, {%1, %1};" : "=l"(uu) : "f"(u));
    return uu;
}
__device__ __forceinline__ unsigned long long pack2(float lo, float hi) {
    unsigned long long r;
    asm("mov.b64 %0, {%1, %2};" : "=l"(r) : "f"(lo), "f"(hi));
    return r;
}
__device__ __forceinline__ float2 unpack2(unsigned long long v) {
    float2 r;
    asm("mov.b64 {%0, %1}, %2;" : "=f"(r.x), "=f"(r.y) : "l"(v));
    return r;
}

__device__ __forceinline__ float sigm(float x) { return 1.f / (1.f + __expf(-x)); }

// -------------------- scoped atomics for the group barrier ------------------
__device__ __forceinline__ unsigned atom_add_acqrel(unsigned* p, unsigned v) {
    unsigned old;
    asm volatile("atom.add.acq_rel.gpu.global.u32 %0, [%1], %2;"
                 : "=r"(old) : "l"(p), "r"(v) : "memory");
    return old;
}
__device__ __forceinline__ unsigned ld_relaxed_g(const unsigned* p) {
    unsigned v;
    asm volatile("ld.relaxed.gpu.global.u32 %0, [%1];" : "=r"(v) : "l"(p) : "memory");
    return v;
}
__device__ __forceinline__ unsigned ld_acquire_g(const unsigned* p) {
    unsigned v;
    asm volatile("ld.acquire.gpu.global.u32 %0, [%1];" : "=r"(v) : "l"(p) : "memory");
    return v;
}
__device__ __forceinline__ void st_relaxed_g(unsigned* p, unsigned v) {
    asm volatile("st.relaxed.gpu.global.u32 [%0], %1;" :: "l"(p), "r"(v) : "memory");
}

// Group barrier (R8-proven): arrive with acq_rel atomic, poll gen with relaxed
// loads + nanosleep backoff, acquire once on exit.
__device__ __forceinline__ void gbar(int g, unsigned target)
{
    __syncthreads();
    if (threadIdx.x == 0) {
        unsigned* cnt = &g_cnt[g * 256];
        unsigned* gen = &g_gen[g * 256];
        unsigned old = atom_add_acqrel(cnt, 1u);
        if (old == GCTAS - 1) {
            st_relaxed_g(cnt, 0u);
            atom_add_acqrel(gen, 1u);
        } else {
            while (ld_relaxed_g(gen) < target) __nanosleep(40);
            (void)ld_acquire_g(gen);
        }
    }
    __syncthreads();
}

// ===========================================================================
// Kernel 1: Xp[s][b][c] = x[b][s][:] . W_g[c] + bias_g[c]   (unchanged, R8)
// ===========================================================================
__global__ __launch_bounds__(256) void pregemm_kernel(
    const float* __restrict__ x,
    const float* __restrict__ Wz, const float* __restrict__ Wr, const float* __restrict__ Wh,
    const float* __restrict__ bz, const float* __restrict__ br, const float* __restrict__ bh)
{
    __shared__ float As[16][132];
    __shared__ float Bs[16][68];

    const int tid = threadIdx.x;
    const int m0  = blockIdx.x * 128;
    const int c0g = blockIdx.y * 64;

    const float* W; const float* bias; int cr;
    if (c0g < 512)       { W = Wz; bias = bz; cr = c0g; }
    else if (c0g < 1024) { W = Wr; bias = br; cr = c0g - 512; }
    else                 { W = Wh; bias = bh; cr = c0g - 1024; }

    const int arow = tid >> 2;
    const int ak   = (tid & 3) << 2;
    const int bcol = tid >> 2;
    const int bk   = (tid & 3) << 2;
    const int ty   = tid >> 4;
    const int tx   = tid & 15;

    const float* xA0 = x + (size_t)(m0 + arow)      * IDIM + ak;
    const float* xA1 = x + (size_t)(m0 + arow + 64) * IDIM + ak;
    const float* wB  = W + (size_t)(cr + bcol)      * IDIM + bk;

    float4 a0 = *(const float4*)(xA0);
    float4 a1 = *(const float4*)(xA1);
    float4 b0 = *(const float4*)(wB);

    unsigned long long acc2[8][2];
#pragma unroll
    for (int i = 0; i < 8; i++) { acc2[i][0] = 0ull; acc2[i][1] = 0ull; }

    for (int kt = 0; kt < IDIM; kt += 16) {
        As[ak+0][arow]    = a0.x; As[ak+1][arow]    = a0.y;
        As[ak+2][arow]    = a0.z; As[ak+3][arow]    = a0.w;
        As[ak+0][arow+64] = a1.x; As[ak+1][arow+64] = a1.y;
        As[ak+2][arow+64] = a1.z; As[ak+3][arow+64] = a1.w;
        Bs[bk+0][bcol] = b0.x; Bs[bk+1][bcol] = b0.y;
        Bs[bk+2][bcol] = b0.z; Bs[bk+3][bcol] = b0.w;
        __syncthreads();

        if (kt < IDIM - 16) {
            a0 = *(const float4*)(xA0 + kt + 16);
            a1 = *(const float4*)(xA1 + kt + 16);
            b0 = *(const float4*)(wB  + kt + 16);
        }

#pragma unroll
        for (int kk = 0; kk < 16; kk++) {
            float4 rA0 = *(const float4*)&As[kk][ty * 8];
            float4 rA1 = *(const float4*)&As[kk][ty * 8 + 4];
            float4 rBf = *(const float4*)&Bs[kk][tx * 4];
            unsigned long long b01 = pack2(rBf.x, rBf.y);
            unsigned long long b23 = pack2(rBf.z, rBf.w);
            unsigned long long s;
            s = splat2(rA0.x); FMA2(acc2[0][0], s, b01); FMA2(acc2[0][1], s, b23);
            s = splat2(rA0.y); FMA2(acc2[1][0], s, b01); FMA2(acc2[1][1], s, b23);
            s = splat2(rA0.z); FMA2(acc2[2][0], s, b01); FMA2(acc2[2][1], s, b23);
            s = splat2(rA0.w); FMA2(acc2[3][0], s, b01); FMA2(acc2[3][1], s, b23);
            s = splat2(rA1.x); FMA2(acc2[4][0], s, b01); FMA2(acc2[4][1], s, b23);
            s = splat2(rA1.y); FMA2(acc2[5][0], s, b01); FMA2(acc2[5][1], s, b23);
            s = splat2(rA1.z); FMA2(acc2[6][0], s, b01); FMA2(acc2[6][1], s, b23);
            s = splat2(rA1.w); FMA2(acc2[7][0], s, b01); FMA2(acc2[7][1], s, b23);
        }
        __syncthreads();
    }

    float4 bv = *(const float4*)(bias + cr + (tx << 2));
#pragma unroll
    for (int i = 0; i < 8; i++) {
        int mm   = m0 + ty * 8 + i;
        int srow = mm & (S_LEN - 1);
        int bb   = mm >> 11;
        size_t off = ((size_t)(srow * BATCH + bb)) * GATE3 + c0g + (tx << 2);
        float2 p01 = unpack2(acc2[i][0]);
        float2 p23 = unpack2(acc2[i][1]);
        float4 v;
        v.x = p01.x + bv.x; v.y = p01.y + bv.y;
        v.z = p23.x + bv.z; v.w = p23.y + bv.w;
        *(float4*)(g_Xp + off) = v;
    }
}

// ===========================================================================
// Kernel 2: persistent GRU scan. Grid = 128 CTAs (8 groups x 16), 256 thr.
// Phase 1 computes BOTH z and r per warp over a 64-k span (merged gates).
// SMEM (floats): Uz[512][32] | Ur[512][32] | Uh[512][32] | hs[512][8] |
//                red[512][8] | zs[256]
// ===========================================================================
#define UZ_OFF  0
#define UR_OFF  16384
#define UH_OFF  32768
#define HS_OFF  49152
#define RED_OFF 53248
#define ZS_OFF  57344
#define SMEM_FLOATS 57600      // 230400 bytes

__global__ __launch_bounds__(256, 1) void scan_kernel(
    const float* __restrict__ Uz, const float* __restrict__ Ur, const float* __restrict__ Uh,
    const float* __restrict__ cz, const float* __restrict__ cr, const float* __restrict__ ch)
{
    extern __shared__ float sm[];
    const int tid  = threadIdx.x;
    const int g    = blockIdx.x >> 4;
    const int ctg  = blockIdx.x & 15;
    const int cbase = ctg * CCOLS;

    // ---- load U tiles transposed into SMEM: Us[k*32 + c] = U[(cbase+c)*512 + k]
    // (one-time; STS conflicts here are paid once and are negligible)
    {
        const float* Us_src[3] = { Uz, Ur, Uh };
        float* Us_dst[3] = { sm + UZ_OFF, sm + UR_OFF, sm + UH_OFF };
#pragma unroll
        for (int gate = 0; gate < 3; gate++) {
            const float* U = Us_src[gate];
            float* D = Us_dst[gate];
            for (int i = tid; i < CCOLS * 128; i += 256) {
                int c  = i >> 7;
                int k4 = (i & 127) << 2;
                float4 v = *(const float4*)(U + (size_t)(cbase + c) * HDIM + k4);
                D[(k4+0)*32 + c] = v.x;
                D[(k4+1)*32 + c] = v.y;
                D[(k4+2)*32 + c] = v.z;
                D[(k4+3)*32 + c] = v.w;
            }
        }
    }

    const int warp = tid >> 5;
    const int lane = tid & 31;
    const int rc = tid >> 3;        // reduction col 0..31
    const int rb = tid & 7;         // reduction batch 0..7
    const int gb = g * NB + rb;
    const int gcol = cbase + rc;

    const float czv = cz[gcol];
    const float crv = cr[gcol];
    const float chv = ch[gcol];

    float* hGrp  = g_hG  + g * (HDIM * NB);
    float* rhGrp = g_rhG + g * (HDIM * NB);

    __syncthreads();

    unsigned gen = 0;

    for (int s = 0; s < S_LEN; s++) {
        // ---------------- phase 1: z and r gates (merged) ----------------
        for (int i = tid; i < 1024; i += 256)
            *(float4*)(sm + HS_OFF + i * 4) = *(const float4*)(hGrp + i * 4);

        const float* xp = g_Xp + ((size_t)s * BATCH + gb) * GATE3 + gcol;
        float xz = xp[0];
        float xr = xp[512];
        float xh = xp[1024];
        __syncthreads();

        {
            const int ks = warp;                  // k-split of 64, both gates
            const float* Uzp = sm + UZ_OFF + ks * 64 * 32 + lane;
            const float* Urp = sm + UR_OFF + ks * 64 * 32 + lane;
            const float* hp  = sm + HS_OFF + ks * 64 * 8;
            unsigned long long az0 = 0, az1 = 0, az2 = 0, az3 = 0;
            unsigned long long ar0 = 0, ar1 = 0, ar2 = 0, ar3 = 0;
#pragma unroll 4
            for (int k = 0; k < 64; k++) {
                unsigned long long uz = splat2(Uzp[k * 32]);
                unsigned long long ur = splat2(Urp[k * 32]);
                ulonglong2 hA = *(const ulonglong2*)(hp + k * 8);
                ulonglong2 hB = *(const ulonglong2*)(hp + k * 8 + 4);
                FMA2(az0, uz, hA.x);
                FMA2(az1, uz, hA.y);
                FMA2(az2, uz, hB.x);
                FMA2(az3, uz, hB.y);
                FMA2(ar0, ur, hA.x);
                FMA2(ar1, ur, hA.y);
                FMA2(ar2, ur, hB.x);
                FMA2(ar3, ur, hB.y);
            }
            float* rpz = sm + RED_OFF + (ks * 32 + lane) * 8;
            float* rpr = sm + RED_OFF + ((8 + ks) * 32 + lane) * 8;
            ulonglong2 z0; z0.x = az0; z0.y = az1;
            ulonglong2 z1; z1.x = az2; z1.y = az3;
            ulonglong2 r0; r0.x = ar0; r0.y = ar1;
            ulonglong2 r1; r1.x = ar2; r1.y = ar3;
            *(ulonglong2*)(rpz)     = z0;
            *(ulonglong2*)(rpz + 4) = z1;
            *(ulonglong2*)(rpr)     = r0;
            *(ulonglong2*)(rpr + 4) = r1;
        }
        __syncthreads();

        const float* rd = sm + RED_OFF;
        float zsum = 0.f, rsum = 0.f;
#pragma unroll
        for (int ks = 0; ks < 8; ks++) {
            zsum += rd[(ks * 32 + rc) * 8 + rb];
            rsum += rd[((8 + ks) * 32 + rc) * 8 + rb];
        }
        float z = sigm(zsum + xz + czv);
        float r = sigm(rsum + xr + crv);
        float hold = sm[HS_OFF + gcol * 8 + rb];
        sm[ZS_OFF + rc * 8 + rb] = z;
        rhGrp[gcol * NB + rb] = r * hold;

        gbar(g, ++gen);

        // ---------------- phase 2: candidate + update ----------------
        for (int i = tid; i < 1024; i += 256)
            *(float4*)(sm + HS_OFF + i * 4) = *(const float4*)(rhGrp + i * 4);
        __syncthreads();

        {
            const int ks = warp;                  // k-split of 64
            const float* Ub = sm + UH_OFF + ks * 64 * 32 + lane;
            const float* hp = sm + HS_OFF + ks * 64 * 8;
            unsigned long long a0 = 0, a1 = 0, a2 = 0, a3 = 0;
#pragma unroll 4
            for (int k = 0; k < 64; k++) {
                unsigned long long uu = splat2(Ub[k * 32]);
                ulonglong2 hA = *(const ulonglong2*)(hp + k * 8);
                ulonglong2 hB = *(const ulonglong2*)(hp + k * 8 + 4);
                FMA2(a0, uu, hA.x);
                FMA2(a1, uu, hA.y);
                FMA2(a2, uu, hB.x);
                FMA2(a3, uu, hB.y);
            }
            float* rp = sm + RED_OFF + (ks * 32 + lane) * 8;
            ulonglong2 s0; s0.x = a0; s0.y = a1;
            ulonglong2 s1; s1.x = a2; s1.y = a3;
            *(ulonglong2*)(rp)     = s0;
            *(ulonglong2*)(rp + 4) = s1;
        }
        __syncthreads();

        const float* rd2 = sm + RED_OFF;
        float hsum = 0.f;
#pragma unroll
        for (int ks = 0; ks < 8; ks++)
            hsum += rd2[(ks * 32 + rc) * 8 + rb];
        float htil = tanhf(hsum + xh + chv);
        float z2 = sm[ZS_OFF + rc * 8 + rb];
        float hnew = hold + z2 * (htil - hold);
        hGrp[gcol * NB + rb] = hnew;

        gbar(g, ++gen);
    }
}

// ===========================================================================
// Kernel 3: out[b][o] = sum_j h[g(b)][j][b&7] * Wf[o][j] + bf[o]
// ===========================================================================
__global__ __launch_bounds__(640) void outgemm_kernel(
    const float* __restrict__ Wf, const float* __restrict__ bf, float* __restrict__ out)
{
    int t = threadIdx.x;
    if (t >= 640) return;
    int b = t / 10, o = t % 10;
    const float* hb = g_hG + (b >> 3) * (HDIM * NB) + (b & 7);
    float acc = 0.f;
#pragma unroll 8
    for (int j = 0; j < HDIM; j++)
        acc += hb[j * NB] * Wf[o * HDIM + j];
    out[b * 10 + o] = acc + bf[o];
}

// ===========================================================================
extern "C" void kernel_launch(void* const* d_in, const int* in_sizes, int n_in,
                              void* d_out, int out_size)
{
    const float* x  = (const float*)d_in[0];
    const float* Wz = (const float*)d_in[1];
    const float* bz = (const float*)d_in[2];
    const float* Uz = (const float*)d_in[3];
    const float* cz = (const float*)d_in[4];
    const float* Wr = (const float*)d_in[5];
    const float* br = (const float*)d_in[6];
    const float* Ur = (const float*)d_in[7];
    const float* cr = (const float*)d_in[8];
    const float* Wh = (const float*)d_in[9];
    const float* bh = (const float*)d_in[10];
    const float* Uh = (const float*)d_in[11];
    const float* ch = (const float*)d_in[12];
    const float* Wf = (const float*)d_in[13];
    const float* bf = (const float*)d_in[14];
    float* out = (float*)d_out;

    void *p_h, *p_cnt, *p_gen;
    cudaGetSymbolAddress(&p_h,   g_hG);
    cudaGetSymbolAddress(&p_cnt, g_cnt);
    cudaGetSymbolAddress(&p_gen, g_gen);

    cudaMemsetAsync(p_h,   0, NGROUPS * HDIM * NB * sizeof(float));
    cudaMemsetAsync(p_cnt, 0, NGROUPS * 256 * sizeof(unsigned int));
    cudaMemsetAsync(p_gen, 0, NGROUPS * 256 * sizeof(unsigned int));

    pregemm_kernel<<<dim3(1024, 24), 256>>>(x, Wz, Wr, Wh, bz, br, bh);

    cudaFuncSetAttribute(scan_kernel, cudaFuncAttributeMaxDynamicSharedMemorySize,
                         SMEM_FLOATS * sizeof(float));
    scan_kernel<<<NGROUPS * GCTAS, 256, SMEM_FLOATS * sizeof(float)>>>(Uz, Ur, Uh, cz, cr, ch);

    outgemm_kernel<<<1, 640>>>(Wf, bf, out);
}